// round 3
// baseline (speedup 1.0000x reference)
#include <cuda_runtime.h>
#include <cuda_bf16.h>
#include <math.h>

#define BATCH 16
#define LSEQ  8192
#define DDIM  256

// softmax weights scratch: 16*8192 floats = 512 KB
__device__ float g_w[BATCH * LSEQ];

// ---------------------------------------------------------------------------
// Stage A: per-batch L2 norms over D, then softmax over L. One block per batch.
// 1024 threads = 32 warps; each warp owns rows l = warp, warp+32, ...
// Row read is fully coalesced (lane i reads float4 at d = i*4 (+128)).
// ---------------------------------------------------------------------------
__global__ __launch_bounds__(1024) void norms_softmax_kernel(const float* __restrict__ x)
{
    const int b   = blockIdx.x;
    const float* xb = x + (size_t)b * LSEQ * DDIM;

    __shared__ float s_norm[LSEQ];   // 32 KB
    __shared__ float s_red[32];

    const int tid  = threadIdx.x;
    const int warp = tid >> 5;
    const int lane = tid & 31;

    // ---- per-row sum of squares ----
    for (int l = warp; l < LSEQ; l += 32) {
        const float4* row = (const float4*)(xb + (size_t)l * DDIM);
        float s = 0.f;
#pragma unroll
        for (int i = 0; i < 2; i++) {
            float4 v = row[lane + 32 * i];
            s += v.x * v.x + v.y * v.y + v.z * v.z + v.w * v.w;
        }
#pragma unroll
        for (int o = 16; o; o >>= 1) s += __shfl_xor_sync(0xffffffffu, s, o);
        if (lane == 0) s_norm[l] = sqrtf(s);
    }
    __syncthreads();

    // ---- max over L ----
    float m = -1e30f;
    for (int l = tid; l < LSEQ; l += 1024) m = fmaxf(m, s_norm[l]);
#pragma unroll
    for (int o = 16; o; o >>= 1) m = fmaxf(m, __shfl_xor_sync(0xffffffffu, m, o));
    if (lane == 0) s_red[warp] = m;
    __syncthreads();
    if (warp == 0) {
        float t = s_red[lane];
#pragma unroll
        for (int o = 16; o; o >>= 1) t = fmaxf(t, __shfl_xor_sync(0xffffffffu, t, o));
        if (lane == 0) s_red[0] = t;
    }
    __syncthreads();
    m = s_red[0];
    __syncthreads();   // protect s_red before reuse

    // ---- exp + sum ----
    float ssum = 0.f;
    for (int l = tid; l < LSEQ; l += 1024) {
        float e = __expf(s_norm[l] - m);
        s_norm[l] = e;
        ssum += e;
    }
#pragma unroll
    for (int o = 16; o; o >>= 1) ssum += __shfl_xor_sync(0xffffffffu, ssum, o);
    if (lane == 0) s_red[warp] = ssum;
    __syncthreads();
    if (warp == 0) {
        float t = s_red[lane];
#pragma unroll
        for (int o = 16; o; o >>= 1) t += __shfl_xor_sync(0xffffffffu, t, o);
        if (lane == 0) s_red[0] = t;
    }
    __syncthreads();
    const float inv = 1.f / s_red[0];

    for (int l = tid; l < LSEQ; l += 1024)
        g_w[b * LSEQ + l] = s_norm[l] * inv;
}

// ---------------------------------------------------------------------------
// Stage B: out[b] = X^T diag(w) X   (256x256, K=8192), symmetric.
// Only the 10 upper-triangular 64x64 tile pairs are computed; off-diagonal
// tiles are mirrored on store. Block = 256 threads (16x16), each thread owns
// a 4x4 micro-tile. K-chunk = 32 rows staged in shared memory; the w weight
// is folded into the A tile at load time.
// ---------------------------------------------------------------------------
#define TK 32

__global__ __launch_bounds__(256) void sym_gemm_kernel(const float* __restrict__ x,
                                                       float* __restrict__ out)
{
    // pair index -> (ti, tj), ti <= tj, 4x4 tiles of 64
    const int TI_[10] = {0,0,0,0,1,1,1,2,2,3};
    const int TJ_[10] = {0,1,2,3,1,2,3,2,3,3};
    const int ti = TI_[blockIdx.x];
    const int tj = TJ_[blockIdx.x];
    const int b  = blockIdx.y;

    const float* xb = x   + (size_t)b * LSEQ * DDIM;
    const float* wb = g_w + (size_t)b * LSEQ;

    __shared__ float As[TK][64];
    __shared__ float Bs[TK][64];

    const int tid = threadIdx.x;
    const int tx  = tid & 15;        // 0..15 -> cols (e)
    const int ty  = tid >> 4;        // 0..15 -> rows (d)

    const int d0 = ti * 64;
    const int e0 = tj * 64;

    // loader mapping: 256 threads cover 16 rows x 64 cols per pass (2 passes)
    const int lr = tid >> 4;         // 0..15
    const int lc = (tid & 15) * 4;   // 0..60

    float acc[4][4] = {};

    for (int l0 = 0; l0 < LSEQ; l0 += TK) {
#pragma unroll
        for (int r = 0; r < TK; r += 16) {
            const int row = lr + r;
            const float wv = wb[l0 + row];
            const float* src = xb + (size_t)(l0 + row) * DDIM;
            float4 a  = *(const float4*)(src + d0 + lc);
            float4 bv = *(const float4*)(src + e0 + lc);
            a.x *= wv; a.y *= wv; a.z *= wv; a.w *= wv;
            *(float4*)&As[row][lc] = a;
            *(float4*)&Bs[row][lc] = bv;
        }
        __syncthreads();

#pragma unroll
        for (int kk = 0; kk < TK; kk++) {
            const float4 a  = *(const float4*)&As[kk][ty * 4];
            const float4 bv = *(const float4*)&Bs[kk][tx * 4];
            acc[0][0] += a.x * bv.x; acc[0][1] += a.x * bv.y;
            acc[0][2] += a.x * bv.z; acc[0][3] += a.x * bv.w;
            acc[1][0] += a.y * bv.x; acc[1][1] += a.y * bv.y;
            acc[1][2] += a.y * bv.z; acc[1][3] += a.y * bv.w;
            acc[2][0] += a.z * bv.x; acc[2][1] += a.z * bv.y;
            acc[2][2] += a.z * bv.z; acc[2][3] += a.z * bv.w;
            acc[3][0] += a.w * bv.x; acc[3][1] += a.w * bv.y;
            acc[3][2] += a.w * bv.z; acc[3][3] += a.w * bv.w;
        }
        __syncthreads();
    }

    float* ob = out + (size_t)b * DDIM * DDIM;
#pragma unroll
    for (int i = 0; i < 4; i++) {
#pragma unroll
        for (int j = 0; j < 4; j++) {
            const int d = d0 + ty * 4 + i;
            const int e = e0 + tx * 4 + j;
            ob[(size_t)d * DDIM + e] = acc[i][j];
            if (ti != tj)
                ob[(size_t)e * DDIM + d] = acc[i][j];
        }
    }
}

extern "C" void kernel_launch(void* const* d_in, const int* in_sizes, int n_in,
                              void* d_out, int out_size)
{
    const float* x = (const float*)d_in[0];
    float* out = (float*)d_out;

    norms_softmax_kernel<<<BATCH, 1024>>>(x);

    dim3 grid(10, BATCH);
    sym_gemm_kernel<<<grid, 256>>>(x, out);
}

// round 5
// speedup vs baseline: 3.2997x; 3.2997x over previous
#include <cuda_runtime.h>
#include <cuda_bf16.h>
#include <cstdint>
#include <math.h>

#define BATCH 16
#define LSEQ  8192
#define DDIM  256

#define KSPLIT 8
#define KRANGE (LSEQ / KSPLIT)     // 1024
#define KC     32
#define CHUNKS (KRANGE / KC)       // 32

// ---------------------------------------------------------------------------
// Static device scratch (no allocation allowed)
// ---------------------------------------------------------------------------
__device__ float g_norm[BATCH * LSEQ];                   // 512 KB
__device__ float g_sw[BATCH * LSEQ];                     // sqrt(softmax w)
__device__ float g_part[BATCH * 3 * KSPLIT * 128 * 128]; // 25 MB split-K partials

// ---------------------------------------------------------------------------
// Helpers
// ---------------------------------------------------------------------------
__device__ __forceinline__ uint32_t smem_u32(const void* p) {
    uint32_t a;
    asm("{ .reg .u64 t; cvta.to.shared.u64 t, %1; cvt.u32.u64 %0, t; }"
        : "=r"(a) : "l"(p));
    return a;
}

__device__ __forceinline__ void ldsm4t(uint32_t* r, uint32_t addr) {
    asm volatile("ldmatrix.sync.aligned.m8n8.x4.trans.shared.b16 {%0,%1,%2,%3}, [%4];"
                 : "=r"(r[0]), "=r"(r[1]), "=r"(r[2]), "=r"(r[3]) : "r"(addr));
}

__device__ __forceinline__ void mma16816(float* c, const uint32_t* a,
                                         uint32_t b0, uint32_t b1) {
    asm volatile(
        "mma.sync.aligned.m16n8k16.row.col.f32.bf16.bf16.f32 "
        "{%0,%1,%2,%3}, {%4,%5,%6,%7}, {%8,%9}, {%0,%1,%2,%3};"
        : "+f"(c[0]), "+f"(c[1]), "+f"(c[2]), "+f"(c[3])
        : "r"(a[0]), "r"(a[1]), "r"(a[2]), "r"(a[3]), "r"(b0), "r"(b1));
}

// ---------------------------------------------------------------------------
// Stage A1: per-row L2 norms.  grid (64, 16), 256 threads.
// ---------------------------------------------------------------------------
__global__ __launch_bounds__(256) void norms_kernel(const float* __restrict__ x)
{
    const int b    = blockIdx.y;
    const int r0   = blockIdx.x * 128;
    const int warp = threadIdx.x >> 5;
    const int lane = threadIdx.x & 31;
    const float* xb = x + (size_t)b * LSEQ * DDIM;

#pragma unroll 4
    for (int i = 0; i < 16; i++) {
        const int l = r0 + warp * 16 + i;
        const float4* row = (const float4*)(xb + (size_t)l * DDIM);
        float4 v1 = row[lane];
        float4 v2 = row[lane + 32];
        float s = v1.x * v1.x + v1.y * v1.y + v1.z * v1.z + v1.w * v1.w
                + v2.x * v2.x + v2.y * v2.y + v2.z * v2.z + v2.w * v2.w;
#pragma unroll
        for (int o = 16; o; o >>= 1) s += __shfl_xor_sync(0xffffffffu, s, o);
        if (lane == 0) g_norm[b * LSEQ + l] = sqrtf(s);
    }
}

// ---------------------------------------------------------------------------
// Stage A2: softmax over L; writes sqrt(w). One block per batch.
// ---------------------------------------------------------------------------
__global__ __launch_bounds__(1024) void softmax_kernel()
{
    const int b = blockIdx.x;
    __shared__ float sn[LSEQ];
    __shared__ float sred[32];

    const int tid  = threadIdx.x;
    const int warp = tid >> 5;
    const int lane = tid & 31;

    float m = -1e30f;
    for (int l = tid; l < LSEQ; l += 1024) {
        float v = g_norm[b * LSEQ + l];
        sn[l] = v;
        m = fmaxf(m, v);
    }
#pragma unroll
    for (int o = 16; o; o >>= 1) m = fmaxf(m, __shfl_xor_sync(0xffffffffu, m, o));
    if (lane == 0) sred[warp] = m;
    __syncthreads();
    if (warp == 0) {
        float t = sred[lane];
#pragma unroll
        for (int o = 16; o; o >>= 1) t = fmaxf(t, __shfl_xor_sync(0xffffffffu, t, o));
        if (lane == 0) sred[0] = t;
    }
    __syncthreads();
    m = sred[0];
    __syncthreads();

    float ssum = 0.f;
    for (int l = tid; l < LSEQ; l += 1024) {
        float e = __expf(sn[l] - m);
        sn[l] = e;
        ssum += e;
    }
#pragma unroll
    for (int o = 16; o; o >>= 1) ssum += __shfl_xor_sync(0xffffffffu, ssum, o);
    if (lane == 0) sred[warp] = ssum;
    __syncthreads();
    if (warp == 0) {
        float t = sred[lane];
#pragma unroll
        for (int o = 16; o; o >>= 1) t += __shfl_xor_sync(0xffffffffu, t, o);
        if (lane == 0) sred[0] = t;
    }
    __syncthreads();
    const float inv = 1.f / sred[0];

    for (int l = tid; l < LSEQ; l += 1024)
        g_sw[b * LSEQ + l] = sqrtf(sn[l] * inv);
}

// ---------------------------------------------------------------------------
// Stage B: bf16 hi/lo split SYRK via mma.sync (HMMA).
// C = Y^T Y, Y[l][d] = sqrt(w_l) x[l][d]. Tile 128x128, 3 upper tiles/batch,
// split-K 8. Block = 256 threads (8 warps), warp tile 64x32.
// SMEM: [KC][136] bf16 rows (272B stride -> conflict-free ldmatrix).
// ---------------------------------------------------------------------------
#define SP  136
#define SPB 272

__global__ __launch_bounds__(256, 2) void tensor_gemm(const float* __restrict__ x)
{
    __shared__ __align__(16) __nv_bfloat16 YaH[KC][SP];
    __shared__ __align__(16) __nv_bfloat16 YaL[KC][SP];
    __shared__ __align__(16) __nv_bfloat16 YbH[KC][SP];
    __shared__ __align__(16) __nv_bfloat16 YbL[KC][SP];

    const int tid  = threadIdx.x;
    const int wid  = tid >> 5;
    const int lane = tid & 31;

    const int tile = blockIdx.x >> 3;       // 0:(0,0) 1:(0,1) 2:(1,1)
    const int s    = blockIdx.x & 7;        // split-K index
    const int b    = blockIdx.y;
    const int ti   = (tile == 2) ? 1 : 0;
    const int tj   = (tile >= 1) ? 1 : 0;
    const bool diag = (ti == tj);

    const float* xb  = x + (size_t)b * LSEQ * DDIM;
    const float* swb = g_sw + b * LSEQ;
    const int lbase  = s * KRANGE;
    const int c0A = ti * 128;
    const int c0B = tj * 128;

    const uint32_t yaH = smem_u32(YaH), yaL = smem_u32(YaL);
    const uint32_t ybH = diag ? yaH : smem_u32(YbH);
    const uint32_t ybL = diag ? yaL : smem_u32(YbL);

    // warp tile position
    const int wy = wid & 1;          // d half (0..1) -> 64
    const int wx = wid >> 1;         // e quarter (0..3) -> 32

    // ldmatrix per-lane offsets (bytes)
    const uint32_t offA = ((lane & 7) + ((lane >> 4) & 1) * 8) * SPB
                        + ((lane >> 3) & 1) * 16;
    const uint32_t offB = ((lane & 7) + ((lane >> 3) & 1) * 8) * SPB
                        + ((lane >> 4) & 1) * 16;

    const uint32_t aBH = yaH + offA + (uint32_t)(wy * 64) * 2;
    const uint32_t aBL = yaL + offA + (uint32_t)(wy * 64) * 2;
    const uint32_t bBH = ybH + offB + (uint32_t)(wx * 32) * 2;
    const uint32_t bBL = ybL + offB + (uint32_t)(wx * 32) * 2;

    float acc[4][4][4];
#pragma unroll
    for (int m = 0; m < 4; m++)
#pragma unroll
        for (int n = 0; n < 4; n++)
#pragma unroll
            for (int q = 0; q < 4; q++) acc[m][n][q] = 0.f;

    for (int c = 0; c < CHUNKS; c++) {
        const int l0 = lbase + c * KC;
        __syncthreads();

        // ---- convert: gmem fp32 -> SMEM bf16 hi/lo (rows = K, cols = D) ----
#pragma unroll
        for (int i = 0; i < 4; i++) {
            const int row = wid * 4 + i;
            const int l   = l0 + row;
            const float wv = swb[l];
            {
                float4 v = ((const float4*)(xb + (size_t)l * DDIM + c0A))[lane];
                v.x *= wv; v.y *= wv; v.z *= wv; v.w *= wv;
                uint32_t h0, h1, lo0, lo1;
                asm("cvt.rn.bf16x2.f32 %0, %1, %2;" : "=r"(h0) : "f"(v.y), "f"(v.x));
                asm("cvt.rn.bf16x2.f32 %0, %1, %2;" : "=r"(h1) : "f"(v.w), "f"(v.z));
                float r0 = v.x - __uint_as_float(h0 << 16);
                float r1 = v.y - __uint_as_float(h0 & 0xFFFF0000u);
                float r2 = v.z - __uint_as_float(h1 << 16);
                float r3 = v.w - __uint_as_float(h1 & 0xFFFF0000u);
                asm("cvt.rn.bf16x2.f32 %0, %1, %2;" : "=r"(lo0) : "f"(r1), "f"(r0));
                asm("cvt.rn.bf16x2.f32 %0, %1, %2;" : "=r"(lo1) : "f"(r3), "f"(r2));
                uint32_t ad = (uint32_t)(row * SP + 4 * lane) * 2;
                asm volatile("st.shared.v2.b32 [%0], {%1,%2};" :: "r"(yaH + ad), "r"(h0), "r"(h1));
                asm volatile("st.shared.v2.b32 [%0], {%1,%2};" :: "r"(yaL + ad), "r"(lo0), "r"(lo1));
            }
            if (!diag) {
                float4 v = ((const float4*)(xb + (size_t)l * DDIM + c0B))[lane];
                v.x *= wv; v.y *= wv; v.z *= wv; v.w *= wv;
                uint32_t h0, h1, lo0, lo1;
                asm("cvt.rn.bf16x2.f32 %0, %1, %2;" : "=r"(h0) : "f"(v.y), "f"(v.x));
                asm("cvt.rn.bf16x2.f32 %0, %1, %2;" : "=r"(h1) : "f"(v.w), "f"(v.z));
                float r0 = v.x - __uint_as_float(h0 << 16);
                float r1 = v.y - __uint_as_float(h0 & 0xFFFF0000u);
                float r2 = v.z - __uint_as_float(h1 << 16);
                float r3 = v.w - __uint_as_float(h1 & 0xFFFF0000u);
                asm("cvt.rn.bf16x2.f32 %0, %1, %2;" : "=r"(lo0) : "f"(r1), "f"(r0));
                asm("cvt.rn.bf16x2.f32 %0, %1, %2;" : "=r"(lo1) : "f"(r3), "f"(r2));
                uint32_t ad = (uint32_t)(row * SP + 4 * lane) * 2;
                asm volatile("st.shared.v2.b32 [%0], {%1,%2};" :: "r"(ybH + ad), "r"(h0), "r"(h1));
                asm volatile("st.shared.v2.b32 [%0], {%1,%2};" :: "r"(ybL + ad), "r"(lo0), "r"(lo1));
            }
        }
        __syncthreads();

        // ---- MMA: 2 k16 steps; products AhBh + AhBl + AlBh ----
#pragma unroll
        for (int kk = 0; kk < 2; kk++) {
            const uint32_t krow = (uint32_t)(kk * 16) * SPB;
            uint32_t ah[4][4], bh[2][4];
#pragma unroll
            for (int m = 0; m < 4; m++) ldsm4t(ah[m], aBH + krow + m * 32);
#pragma unroll
            for (int j = 0; j < 2; j++) ldsm4t(bh[j], bBH + krow + j * 32);
#pragma unroll
            for (int m = 0; m < 4; m++)
#pragma unroll
                for (int j = 0; j < 2; j++) {
                    mma16816(acc[m][j * 2 + 0], ah[m], bh[j][0], bh[j][1]);
                    mma16816(acc[m][j * 2 + 1], ah[m], bh[j][2], bh[j][3]);
                }
            {
                uint32_t bl[2][4];
#pragma unroll
                for (int j = 0; j < 2; j++) ldsm4t(bl[j], bBL + krow + j * 32);
#pragma unroll
                for (int m = 0; m < 4; m++)
#pragma unroll
                    for (int j = 0; j < 2; j++) {
                        mma16816(acc[m][j * 2 + 0], ah[m], bl[j][0], bl[j][1]);
                        mma16816(acc[m][j * 2 + 1], ah[m], bl[j][2], bl[j][3]);
                    }
            }
            {
                uint32_t al[4][4];
#pragma unroll
                for (int m = 0; m < 4; m++) ldsm4t(al[m], aBL + krow + m * 32);
#pragma unroll
                for (int m = 0; m < 4; m++)
#pragma unroll
                    for (int j = 0; j < 2; j++) {
                        mma16816(acc[m][j * 2 + 0], al[m], bh[j][0], bh[j][1]);
                        mma16816(acc[m][j * 2 + 1], al[m], bh[j][2], bh[j][3]);
                    }
            }
        }
    }

    // ---- epilogue: write split-K partial tile ----
    float* dst = g_part + (((size_t)b * 3 + tile) * KSPLIT + s) * (128 * 128);
#pragma unroll
    for (int m = 0; m < 4; m++)
#pragma unroll
        for (int j = 0; j < 2; j++)
#pragma unroll
            for (int n = 0; n < 2; n++) {
                const int d = wy * 64 + m * 16 + (lane >> 2);
                const int e = wx * 32 + j * 16 + n * 8 + (lane & 3) * 2;
                float* c = acc[m][j * 2 + n];
                *(float2*)(dst + d * 128 + e)       = make_float2(c[0], c[1]);
                *(float2*)(dst + (d + 8) * 128 + e) = make_float2(c[2], c[3]);
            }
}

// ---------------------------------------------------------------------------
// Split-K reduce + symmetric mirror. idx over [B][3 tiles][128*128].
// ---------------------------------------------------------------------------
__global__ __launch_bounds__(256) void reduce_kernel(float* __restrict__ out)
{
    const int idx = blockIdx.x * 256 + threadIdx.x;
    const int b   = idx / (3 * 16384);
    const int rem = idx % (3 * 16384);
    const int t   = rem >> 14;
    const int dl  = (rem >> 7) & 127;
    const int el  = rem & 127;

    const float* p = g_part + (((size_t)b * 3 + t) * KSPLIT) * 16384 + dl * 128 + el;
    float v = 0.f;
#pragma unroll
    for (int s = 0; s < KSPLIT; s++) v += p[s * 16384];

    float* ob = out + (size_t)b * DDIM * DDIM;
    if (t == 0) {
        ob[dl * DDIM + el] = v;
    } else if (t == 2) {
        ob[(128 + dl) * DDIM + (128 + el)] = v;
    } else {
        ob[dl * DDIM + (128 + el)] = v;
        ob[(128 + el) * DDIM + dl] = v;     // mirror
    }
}

// ---------------------------------------------------------------------------
extern "C" void kernel_launch(void* const* d_in, const int* in_sizes, int n_in,
                              void* d_out, int out_size)
{
    const float* x = (const float*)d_in[0];
    float* out = (float*)d_out;

    norms_kernel<<<dim3(64, BATCH), 256>>>(x);
    softmax_kernel<<<BATCH, 1024>>>();
    tensor_gemm<<<dim3(3 * KSPLIT, BATCH), 256>>>(x);
    reduce_kernel<<<BATCH * 3 * 16384 / 256, 256>>>(out);
}

// round 6
// speedup vs baseline: 4.1578x; 1.2600x over previous
#include <cuda_runtime.h>
#include <cuda_bf16.h>
#include <cstdint>
#include <math.h>

#define BATCH 16
#define LSEQ  8192
#define DDIM  256

#define KSPLIT 8
#define KRANGE (LSEQ / KSPLIT)     // 1024
#define KC     32
#define CHUNKS (KRANGE / KC)       // 32

// ---------------------------------------------------------------------------
// Static device scratch (no allocation allowed)
// ---------------------------------------------------------------------------
__device__ float g_norm[BATCH * LSEQ];                   // 512 KB
__device__ float g_sw[BATCH * LSEQ];                     // sqrt(softmax w)
__device__ float g_part[BATCH * 3 * KSPLIT * 128 * 128]; // 25 MB split-K partials

// ---------------------------------------------------------------------------
// Helpers
// ---------------------------------------------------------------------------
__device__ __forceinline__ uint32_t smem_u32(const void* p) {
    uint32_t a;
    asm("{ .reg .u64 t; cvta.to.shared.u64 t, %1; cvt.u32.u64 %0, t; }"
        : "=r"(a) : "l"(p));
    return a;
}

__device__ __forceinline__ void ldsm4t(uint32_t* r, uint32_t addr) {
    asm volatile("ldmatrix.sync.aligned.m8n8.x4.trans.shared.b16 {%0,%1,%2,%3}, [%4];"
                 : "=r"(r[0]), "=r"(r[1]), "=r"(r[2]), "=r"(r[3]) : "r"(addr));
}

__device__ __forceinline__ void mma16816(float* c, const uint32_t* a,
                                         uint32_t b0, uint32_t b1) {
    asm volatile(
        "mma.sync.aligned.m16n8k16.row.col.f32.bf16.bf16.f32 "
        "{%0,%1,%2,%3}, {%4,%5,%6,%7}, {%8,%9}, {%0,%1,%2,%3};"
        : "+f"(c[0]), "+f"(c[1]), "+f"(c[2]), "+f"(c[3])
        : "r"(a[0]), "r"(a[1]), "r"(a[2]), "r"(a[3]), "r"(b0), "r"(b1));
}

// bf16 hi/lo split of a scaled float4 -> packed pairs
__device__ __forceinline__ void split4(float4 v, float wv,
                                       uint32_t& h0, uint32_t& h1,
                                       uint32_t& lo0, uint32_t& lo1) {
    v.x *= wv; v.y *= wv; v.z *= wv; v.w *= wv;
    asm("cvt.rn.bf16x2.f32 %0, %1, %2;" : "=r"(h0) : "f"(v.y), "f"(v.x));
    asm("cvt.rn.bf16x2.f32 %0, %1, %2;" : "=r"(h1) : "f"(v.w), "f"(v.z));
    float r0 = v.x - __uint_as_float(h0 << 16);
    float r1 = v.y - __uint_as_float(h0 & 0xFFFF0000u);
    float r2 = v.z - __uint_as_float(h1 << 16);
    float r3 = v.w - __uint_as_float(h1 & 0xFFFF0000u);
    asm("cvt.rn.bf16x2.f32 %0, %1, %2;" : "=r"(lo0) : "f"(r1), "f"(r0));
    asm("cvt.rn.bf16x2.f32 %0, %1, %2;" : "=r"(lo1) : "f"(r3), "f"(r2));
}

// ---------------------------------------------------------------------------
// Stage A1: per-row L2 norms.  grid (64, 16), 256 threads.
// ---------------------------------------------------------------------------
__global__ __launch_bounds__(256) void norms_kernel(const float* __restrict__ x)
{
    const int b    = blockIdx.y;
    const int r0   = blockIdx.x * 128;
    const int warp = threadIdx.x >> 5;
    const int lane = threadIdx.x & 31;
    const float* xb = x + (size_t)b * LSEQ * DDIM;

#pragma unroll 4
    for (int i = 0; i < 16; i++) {
        const int l = r0 + warp * 16 + i;
        const float4* row = (const float4*)(xb + (size_t)l * DDIM);
        float4 v1 = row[lane];
        float4 v2 = row[lane + 32];
        float s = v1.x * v1.x + v1.y * v1.y + v1.z * v1.z + v1.w * v1.w
                + v2.x * v2.x + v2.y * v2.y + v2.z * v2.z + v2.w * v2.w;
#pragma unroll
        for (int o = 16; o; o >>= 1) s += __shfl_xor_sync(0xffffffffu, s, o);
        if (lane == 0) g_norm[b * LSEQ + l] = sqrtf(s);
    }
}

// ---------------------------------------------------------------------------
// Stage A2: softmax over L; writes sqrt(w). One block per batch.
// ---------------------------------------------------------------------------
__global__ __launch_bounds__(1024) void softmax_kernel()
{
    const int b = blockIdx.x;
    __shared__ float sn[LSEQ];
    __shared__ float sred[32];

    const int tid  = threadIdx.x;
    const int warp = tid >> 5;
    const int lane = tid & 31;

    float m = -1e30f;
    for (int l = tid; l < LSEQ; l += 1024) {
        float v = g_norm[b * LSEQ + l];
        sn[l] = v;
        m = fmaxf(m, v);
    }
#pragma unroll
    for (int o = 16; o; o >>= 1) m = fmaxf(m, __shfl_xor_sync(0xffffffffu, m, o));
    if (lane == 0) sred[warp] = m;
    __syncthreads();
    if (warp == 0) {
        float t = sred[lane];
#pragma unroll
        for (int o = 16; o; o >>= 1) t = fmaxf(t, __shfl_xor_sync(0xffffffffu, t, o));
        if (lane == 0) sred[0] = t;
    }
    __syncthreads();
    m = sred[0];
    __syncthreads();

    float ssum = 0.f;
    for (int l = tid; l < LSEQ; l += 1024) {
        float e = __expf(sn[l] - m);
        sn[l] = e;
        ssum += e;
    }
#pragma unroll
    for (int o = 16; o; o >>= 1) ssum += __shfl_xor_sync(0xffffffffu, ssum, o);
    if (lane == 0) sred[warp] = ssum;
    __syncthreads();
    if (warp == 0) {
        float t = sred[lane];
#pragma unroll
        for (int o = 16; o; o >>= 1) t += __shfl_xor_sync(0xffffffffu, t, o);
        if (lane == 0) sred[0] = t;
    }
    __syncthreads();
    const float inv = 1.f / sred[0];

    for (int l = tid; l < LSEQ; l += 1024)
        g_sw[b * LSEQ + l] = sqrtf(sn[l] * inv);
}

// ---------------------------------------------------------------------------
// Stage B: bf16 hi/lo split SYRK via mma.sync, pipelined.
//  - register prefetch of next K-chunk's gmem (LDG hidden behind MMA)
//  - ping-pong bf16 SMEM buffers -> ONE __syncthreads per chunk
// Block = 256 threads (8 warps), CTA tile 128x128, warp tile 64x32.
// SMEM rows: 136 bf16 = 272B stride (16B-aligned, conflict-free ldmatrix).
// ---------------------------------------------------------------------------
#define SP   136
#define SPB  272
#define ABYTES (KC * SPB)          // 8704 bytes per array
// dynamic smem layout: [p][aH, aL, bH, bL]
#define SM_TOT (2 * 4 * ABYTES)    // 69632

__global__ __launch_bounds__(256, 2) void tensor_gemm(const float* __restrict__ x)
{
    extern __shared__ __align__(16) char dsm[];
    const uint32_t sb = smem_u32(dsm);

    const int tid  = threadIdx.x;
    const int wid  = tid >> 5;
    const int lane = tid & 31;

    const int tile = blockIdx.x >> 3;       // 0:(0,0) 1:(0,1) 2:(1,1)
    const int s    = blockIdx.x & 7;        // split-K index
    const int b    = blockIdx.y;
    const int ti   = (tile == 2) ? 1 : 0;
    const int tj   = (tile >= 1) ? 1 : 0;
    const bool diag = (ti == tj);

    const float* xb  = x + (size_t)b * LSEQ * DDIM;
    const float* swb = g_sw + b * LSEQ;
    const int lbase  = s * KRANGE;
    const int c0A = ti * 128;
    const int c0B = tj * 128;

    // warp tile position
    const int wy = wid & 1;          // d half -> 64
    const int wx = wid >> 1;         // e quarter -> 32

    // ldmatrix per-lane offsets (bytes)
    const uint32_t offA = ((lane & 7) + ((lane >> 4) & 1) * 8) * SPB
                        + ((lane >> 3) & 1) * 16;
    const uint32_t offB = ((lane & 7) + ((lane >> 3) & 1) * 8) * SPB
                        + ((lane >> 4) & 1) * 16;

    // store offset within an array for this thread's (row, 4*lane) slot
    const int crow = wid * 4;                               // first of 4 rows
    const uint32_t stoff = (uint32_t)(4 * lane) * 2;        // byte offset in row

    float acc[4][4][4];
#pragma unroll
    for (int m = 0; m < 4; m++)
#pragma unroll
        for (int n = 0; n < 4; n++)
#pragma unroll
            for (int q = 0; q < 4; q++) acc[m][n][q] = 0.f;

    // -------- prefetch registers --------
    float4 pa[4], pb[4];
    float  pw[4];

    {
        const int l0 = lbase;
#pragma unroll
        for (int i = 0; i < 4; i++) {
            const int l = l0 + crow + i;
            pw[i] = swb[l];
            pa[i] = ((const float4*)(xb + (size_t)l * DDIM + c0A))[lane];
            if (!diag)
                pb[i] = ((const float4*)(xb + (size_t)l * DDIM + c0B))[lane];
        }
    }

    for (int c = 0; c < CHUNKS; c++) {
        const uint32_t base = sb + (uint32_t)(c & 1) * (4 * ABYTES);
        const uint32_t yaH = base;
        const uint32_t yaL = base + ABYTES;
        const uint32_t ybH = diag ? yaH : base + 2 * ABYTES;
        const uint32_t ybL = diag ? yaL : base + 3 * ABYTES;

        // ---- convert prefetched regs -> SMEM bf16 hi/lo ----
#pragma unroll
        for (int i = 0; i < 4; i++) {
            const uint32_t rowoff = (uint32_t)((crow + i) * SPB) + stoff;
            uint32_t h0, h1, lo0, lo1;
            split4(pa[i], pw[i], h0, h1, lo0, lo1);
            asm volatile("st.shared.v2.b32 [%0], {%1,%2};" :: "r"(yaH + rowoff), "r"(h0), "r"(h1));
            asm volatile("st.shared.v2.b32 [%0], {%1,%2};" :: "r"(yaL + rowoff), "r"(lo0), "r"(lo1));
            if (!diag) {
                split4(pb[i], pw[i], h0, h1, lo0, lo1);
                asm volatile("st.shared.v2.b32 [%0], {%1,%2};" :: "r"(ybH + rowoff), "r"(h0), "r"(h1));
                asm volatile("st.shared.v2.b32 [%0], {%1,%2};" :: "r"(ybL + rowoff), "r"(lo0), "r"(lo1));
            }
        }
        __syncthreads();

        // ---- issue next chunk's LDGs (latency hides behind MMA below) ----
        if (c + 1 < CHUNKS) {
            const int l0 = lbase + (c + 1) * KC;
#pragma unroll
            for (int i = 0; i < 4; i++) {
                const int l = l0 + crow + i;
                pw[i] = swb[l];
                pa[i] = ((const float4*)(xb + (size_t)l * DDIM + c0A))[lane];
                if (!diag)
                    pb[i] = ((const float4*)(xb + (size_t)l * DDIM + c0B))[lane];
            }
        }

        // ---- MMA: 2 k16 steps; products AhBh + AhBl + AlBh ----
        const uint32_t aBH = yaH + offA + (uint32_t)(wy * 64) * 2;
        const uint32_t aBL = yaL + offA + (uint32_t)(wy * 64) * 2;
        const uint32_t bBH = ybH + offB + (uint32_t)(wx * 32) * 2;
        const uint32_t bBL = ybL + offB + (uint32_t)(wx * 32) * 2;

#pragma unroll
        for (int kk = 0; kk < 2; kk++) {
            const uint32_t krow = (uint32_t)(kk * 16) * SPB;
            uint32_t ah[4][4], bh[2][4];
#pragma unroll
            for (int m = 0; m < 4; m++) ldsm4t(ah[m], aBH + krow + m * 32);
#pragma unroll
            for (int j = 0; j < 2; j++) ldsm4t(bh[j], bBH + krow + j * 32);
#pragma unroll
            for (int m = 0; m < 4; m++)
#pragma unroll
                for (int j = 0; j < 2; j++) {
                    mma16816(acc[m][j * 2 + 0], ah[m], bh[j][0], bh[j][1]);
                    mma16816(acc[m][j * 2 + 1], ah[m], bh[j][2], bh[j][3]);
                }
            {
                uint32_t bl[2][4];
#pragma unroll
                for (int j = 0; j < 2; j++) ldsm4t(bl[j], bBL + krow + j * 32);
#pragma unroll
                for (int m = 0; m < 4; m++)
#pragma unroll
                    for (int j = 0; j < 2; j++) {
                        mma16816(acc[m][j * 2 + 0], ah[m], bl[j][0], bl[j][1]);
                        mma16816(acc[m][j * 2 + 1], ah[m], bl[j][2], bl[j][3]);
                    }
            }
            {
                uint32_t al[4][4];
#pragma unroll
                for (int m = 0; m < 4; m++) ldsm4t(al[m], aBL + krow + m * 32);
#pragma unroll
                for (int m = 0; m < 4; m++)
#pragma unroll
                    for (int j = 0; j < 2; j++) {
                        mma16816(acc[m][j * 2 + 0], al[m], bh[j][0], bh[j][1]);
                        mma16816(acc[m][j * 2 + 1], al[m], bh[j][2], bh[j][3]);
                    }
            }
        }
        // no second barrier: next convert writes the OTHER buffer set
    }

    // ---- epilogue: write split-K partial tile ----
    float* dst = g_part + (((size_t)b * 3 + tile) * KSPLIT + s) * (128 * 128);
#pragma unroll
    for (int m = 0; m < 4; m++)
#pragma unroll
        for (int j = 0; j < 2; j++)
#pragma unroll
            for (int n = 0; n < 2; n++) {
                const int d = wy * 64 + m * 16 + (lane >> 2);
                const int e = wx * 32 + j * 16 + n * 8 + (lane & 3) * 2;
                float* cc = acc[m][j * 2 + n];
                *(float2*)(dst + d * 128 + e)       = make_float2(cc[0], cc[1]);
                *(float2*)(dst + (d + 8) * 128 + e) = make_float2(cc[2], cc[3]);
            }
}

// ---------------------------------------------------------------------------
// Split-K reduce + symmetric mirror. idx over [B][3 tiles][128*128].
// ---------------------------------------------------------------------------
__global__ __launch_bounds__(256) void reduce_kernel(float* __restrict__ out)
{
    const int idx = blockIdx.x * 256 + threadIdx.x;
    const int b   = idx / (3 * 16384);
    const int rem = idx % (3 * 16384);
    const int t   = rem >> 14;
    const int dl  = (rem >> 7) & 127;
    const int el  = rem & 127;

    const float* p = g_part + (((size_t)b * 3 + t) * KSPLIT) * 16384 + dl * 128 + el;
    float v = 0.f;
#pragma unroll
    for (int s = 0; s < KSPLIT; s++) v += p[s * 16384];

    float* ob = out + (size_t)b * DDIM * DDIM;
    if (t == 0) {
        ob[dl * DDIM + el] = v;
    } else if (t == 2) {
        ob[(128 + dl) * DDIM + (128 + el)] = v;
    } else {
        ob[dl * DDIM + (128 + el)] = v;
        ob[(128 + el) * DDIM + dl] = v;     // mirror
    }
}

// ---------------------------------------------------------------------------
extern "C" void kernel_launch(void* const* d_in, const int* in_sizes, int n_in,
                              void* d_out, int out_size)
{
    const float* x = (const float*)d_in[0];
    float* out = (float*)d_out;

    cudaFuncSetAttribute(tensor_gemm, cudaFuncAttributeMaxDynamicSharedMemorySize, SM_TOT);

    norms_kernel<<<dim3(64, BATCH), 256>>>(x);
    softmax_kernel<<<BATCH, 1024>>>();
    tensor_gemm<<<dim3(3 * KSPLIT, BATCH), 256, SM_TOT>>>(x);
    reduce_kernel<<<BATCH * 3 * 16384 / 256, 256>>>(out);
}